// round 1
// baseline (speedup 1.0000x reference)
#include <cuda_runtime.h>

// Problem constants
#define NB    16
#define HW    (544*960)          // 522240 gray pixels per batch
#define HW4   (HW/4)             // 130560 float4 per channel per batch
#define TPB   256
#define BPB   51                 // blocks per batch
#define ITERS (HW4/(TPB*BPB))    // 10 (exact: 130560 = 256*51*10)
#define NPART (NB*BPB)           // 816

// Partial accumulators — every slot written every launch (no zeroing needed)
__device__ float g_psum[NPART];
__device__ int   g_pbright[NPART];
__device__ int   g_pdark[NPART];

__global__ __launch_bounds__(TPB) void reduce_kernel(const float* __restrict__ img) {
    const int blk   = blockIdx.x;
    const int batch = blk / BPB;
    const int bpos  = blk % BPB;

    const float4* __restrict__ c0 = (const float4*)(img + (size_t)batch * 3 * HW);
    const float4* __restrict__ c1 = c0 + HW4;
    const float4* __restrict__ c2 = c1 + HW4;

    const int base = bpos * (TPB * ITERS) + threadIdx.x;

    float sum = 0.0f;
    int nb = 0, nd = 0;

    #pragma unroll
    for (int i = 0; i < ITERS; i++) {
        const int idx = base + i * TPB;
        float4 a = c0[idx];
        float4 b = c1[idx];
        float4 c = c2[idx];

        float g0 = (a.x + b.x + c.x) * (1.0f/3.0f);
        float g1 = (a.y + b.y + c.y) * (1.0f/3.0f);
        float g2 = (a.z + b.z + c.z) * (1.0f/3.0f);
        float g3 = (a.w + b.w + c.w) * (1.0f/3.0f);

        sum += g0 + g1 + g2 + g3;
        nb += (g0 >= 0.75f && g0 <= 1.0f);
        nb += (g1 >= 0.75f && g1 <= 1.0f);
        nb += (g2 >= 0.75f && g2 <= 1.0f);
        nb += (g3 >= 0.75f && g3 <= 1.0f);
        nd += (g0 >= 0.0f && g0 < 0.25f);
        nd += (g1 >= 0.0f && g1 < 0.25f);
        nd += (g2 >= 0.0f && g2 < 0.25f);
        nd += (g3 >= 0.0f && g3 < 0.25f);
    }

    // Warp reduce
    #pragma unroll
    for (int o = 16; o > 0; o >>= 1) {
        sum += __shfl_down_sync(0xFFFFFFFFu, sum, o);
        nb  += __shfl_down_sync(0xFFFFFFFFu, nb, o);
        nd  += __shfl_down_sync(0xFFFFFFFFu, nd, o);
    }

    // Block reduce across 8 warps
    __shared__ float ssum[TPB/32];
    __shared__ int   sbr[TPB/32], sdk[TPB/32];
    const int wid = threadIdx.x >> 5;
    const int lane = threadIdx.x & 31;
    if (lane == 0) { ssum[wid] = sum; sbr[wid] = nb; sdk[wid] = nd; }
    __syncthreads();
    if (wid == 0) {
        float s = (lane < TPB/32) ? ssum[lane] : 0.0f;
        int b_ = (lane < TPB/32) ? sbr[lane] : 0;
        int d_ = (lane < TPB/32) ? sdk[lane] : 0;
        #pragma unroll
        for (int o = 4; o > 0; o >>= 1) {
            s  += __shfl_down_sync(0xFFFFFFFFu, s, o);
            b_ += __shfl_down_sync(0xFFFFFFFFu, b_, o);
            d_ += __shfl_down_sync(0xFFFFFFFFu, d_, o);
        }
        if (lane == 0) {
            g_psum[blk]    = s;
            g_pbright[blk] = b_;
            g_pdark[blk]   = d_;
        }
    }
}

__global__ __launch_bounds__(512) void finalize_kernel(const float* __restrict__ e1in,
                                                       const float* __restrict__ e2in,
                                                       float* __restrict__ out) {
    const int wid  = threadIdx.x >> 5;  // one warp per batch (16 warps used)
    const int lane = threadIdx.x & 31;
    __shared__ float s_bavg[NB], s_gap[NB];

    if (wid < NB) {
        float sum = 0.0f;
        int nb = 0, nd = 0;
        for (int i = lane; i < BPB; i += 32) {
            sum += g_psum[wid * BPB + i];
            nb  += g_pbright[wid * BPB + i];
            nd  += g_pdark[wid * BPB + i];
        }
        #pragma unroll
        for (int o = 16; o > 0; o >>= 1) {
            sum += __shfl_down_sync(0xFFFFFFFFu, sum, o);
            nb  += __shfl_down_sync(0xFFFFFFFFu, nb, o);
            nd  += __shfl_down_sync(0xFFFFFFFFu, nd, o);
        }
        if (lane == 0) {
            float dr   = (float)nb / ((float)nd + 1e-5f);
            float bavg = sum * (1.0f / (float)HW);
            float g = 0.5f;
            float gap;
            if (dr > 1.0f && bavg > 0.4f && bavg < 0.6f)      gap = g * 2.0f;
            else if (bavg <= 0.3f)                            gap = g * 0.5f;
            else if (bavg >= 0.7f)                            gap = g * 0.5f;
            else if (dr <= 1.0f && bavg > 0.3f && bavg < 0.7f) gap = g * 0.75f;
            else                                              gap = 0.0f;
            s_bavg[wid] = bavg;
            s_gap[wid]  = gap;
            out[0 * NB + wid] = dr;
            out[1 * NB + wid] = bavg;
            out[2 * NB + wid] = gap;
        }
    }
    __syncthreads();

    if (threadIdx.x < NB) {
        const int b = threadIdx.x;
        const float bl = s_bavg[NB - 1];
        const float gl = s_gap[NB - 1];
        const float s  = 1.7f;
        float e1, e2;
        if (bl <= 0.25f) {
            e1 = e1in[b] + 0.5f * gl * s;
            e2 = e2in[b] + 0.5f * gl * s;
        } else if (bl >= 0.75f) {
            e1 = e1in[b] - 0.5f * gl * s;
            e2 = e2in[b] - 0.5f * gl * s;
        } else {
            e1 = e1in[b] - 0.3f * gl;
            e2 = e2in[b] + 0.7f * gl;
        }
        out[3 * NB + b] = e1;
        out[4 * NB + b] = e2;
    }
}

extern "C" void kernel_launch(void* const* d_in, const int* in_sizes, int n_in,
                              void* d_out, int out_size) {
    const float* img  = (const float*)d_in[0];
    const float* e1in = (const float*)d_in[1];
    const float* e2in = (const float*)d_in[2];
    float* out = (float*)d_out;

    reduce_kernel<<<NB * BPB, TPB>>>(img);
    finalize_kernel<<<1, 512>>>(e1in, e2in, out);
}

// round 2
// speedup vs baseline: 1.2780x; 1.2780x over previous
#include <cuda_runtime.h>

// Problem constants
#define NB    16
#define HW    (544*960)          // 522240 gray pixels per batch
#define HW4   (HW/4)             // 130560 float4 per channel per batch
#define TPB   256
#define BPB   51                 // blocks per batch
#define ITERS (HW4/(TPB*BPB))    // 10 (exact: 130560 = 256*51*10)
#define NPART (NB*BPB)           // 816

// Partial accumulators — every slot written every launch (no zeroing needed)
__device__ float g_psum[NPART];
__device__ int   g_pbright[NPART];
__device__ int   g_pdark[NPART];
__device__ int   g_ticket = 0;   // reset to 0 by the last block each launch

__global__ __launch_bounds__(TPB) void fused_kernel(const float* __restrict__ img,
                                                    const float* __restrict__ e1in,
                                                    const float* __restrict__ e2in,
                                                    float* __restrict__ out) {
    const int blk   = blockIdx.x;
    const int batch = blk / BPB;
    const int bpos  = blk % BPB;

    const float4* __restrict__ c0 = (const float4*)(img + (size_t)batch * 3 * HW);
    const float4* __restrict__ c1 = c0 + HW4;
    const float4* __restrict__ c2 = c1 + HW4;

    const int base = bpos * (TPB * ITERS) + threadIdx.x;

    float sum = 0.0f;
    int nb = 0, nd = 0;

    #pragma unroll
    for (int i = 0; i < ITERS; i++) {
        const int idx = base + i * TPB;
        float4 a = c0[idx];
        float4 b = c1[idx];
        float4 c = c2[idx];

        float g0 = (a.x + b.x + c.x) * (1.0f/3.0f);
        float g1 = (a.y + b.y + c.y) * (1.0f/3.0f);
        float g2 = (a.z + b.z + c.z) * (1.0f/3.0f);
        float g3 = (a.w + b.w + c.w) * (1.0f/3.0f);

        sum += g0 + g1 + g2 + g3;
        nb += (g0 >= 0.75f && g0 <= 1.0f);
        nb += (g1 >= 0.75f && g1 <= 1.0f);
        nb += (g2 >= 0.75f && g2 <= 1.0f);
        nb += (g3 >= 0.75f && g3 <= 1.0f);
        nd += (g0 >= 0.0f && g0 < 0.25f);
        nd += (g1 >= 0.0f && g1 < 0.25f);
        nd += (g2 >= 0.0f && g2 < 0.25f);
        nd += (g3 >= 0.0f && g3 < 0.25f);
    }

    // Warp reduce
    #pragma unroll
    for (int o = 16; o > 0; o >>= 1) {
        sum += __shfl_down_sync(0xFFFFFFFFu, sum, o);
        nb  += __shfl_down_sync(0xFFFFFFFFu, nb, o);
        nd  += __shfl_down_sync(0xFFFFFFFFu, nd, o);
    }

    // Block reduce across 8 warps
    __shared__ float ssum[TPB/32];
    __shared__ int   sbr[TPB/32], sdk[TPB/32];
    __shared__ int   s_is_last;
    const int wid  = threadIdx.x >> 5;
    const int lane = threadIdx.x & 31;
    if (lane == 0) { ssum[wid] = sum; sbr[wid] = nb; sdk[wid] = nd; }
    __syncthreads();
    if (wid == 0) {
        float s = (lane < TPB/32) ? ssum[lane] : 0.0f;
        int b_ = (lane < TPB/32) ? sbr[lane] : 0;
        int d_ = (lane < TPB/32) ? sdk[lane] : 0;
        #pragma unroll
        for (int o = 4; o > 0; o >>= 1) {
            s  += __shfl_down_sync(0xFFFFFFFFu, s, o);
            b_ += __shfl_down_sync(0xFFFFFFFFu, b_, o);
            d_ += __shfl_down_sync(0xFFFFFFFFu, d_, o);
        }
        if (lane == 0) {
            g_psum[blk]    = s;
            g_pbright[blk] = b_;
            g_pdark[blk]   = d_;
            __threadfence();
            int t = atomicAdd(&g_ticket, 1);
            s_is_last = (t == NPART - 1);
        }
    }
    __syncthreads();

    if (!s_is_last) return;

    // ---- Last block: finalize. 16 threads per batch (256 = 16*16). ----
    __shared__ float s_bavg[NB], s_gap[NB];

    const int b   = threadIdx.x >> 4;   // batch 0..15
    const int sub = threadIdx.x & 15;

    float fsum = 0.0f;
    int fb = 0, fd = 0;
    #pragma unroll
    for (int i = sub; i < BPB; i += 16) {
        fsum += g_psum[b * BPB + i];
        fb   += g_pbright[b * BPB + i];
        fd   += g_pdark[b * BPB + i];
    }
    // reduce within the 16-thread group (contiguous lanes in a warp)
    #pragma unroll
    for (int o = 8; o > 0; o >>= 1) {
        fsum += __shfl_down_sync(0xFFFFFFFFu, fsum, o, 16);
        fb   += __shfl_down_sync(0xFFFFFFFFu, fb, o, 16);
        fd   += __shfl_down_sync(0xFFFFFFFFu, fd, o, 16);
    }
    if (sub == 0) {
        float dr   = (float)fb / ((float)fd + 1e-5f);
        float bavg = fsum * (1.0f / (float)HW);
        float g = 0.5f;
        float gap;
        if (dr > 1.0f && bavg > 0.4f && bavg < 0.6f)       gap = g * 2.0f;
        else if (bavg <= 0.3f)                             gap = g * 0.5f;
        else if (bavg >= 0.7f)                             gap = g * 0.5f;
        else if (dr <= 1.0f && bavg > 0.3f && bavg < 0.7f) gap = g * 0.75f;
        else                                               gap = 0.0f;
        s_bavg[b] = bavg;
        s_gap[b]  = gap;
        out[0 * NB + b] = dr;
        out[1 * NB + b] = bavg;
        out[2 * NB + b] = gap;
    }
    __syncthreads();

    if (threadIdx.x < NB) {
        const int bb = threadIdx.x;
        const float bl = s_bavg[NB - 1];
        const float gl = s_gap[NB - 1];
        const float sc = 1.7f;
        float e1, e2;
        if (bl <= 0.25f) {
            e1 = e1in[bb] + 0.5f * gl * sc;
            e2 = e2in[bb] + 0.5f * gl * sc;
        } else if (bl >= 0.75f) {
            e1 = e1in[bb] - 0.5f * gl * sc;
            e2 = e2in[bb] - 0.5f * gl * sc;
        } else {
            e1 = e1in[bb] - 0.3f * gl;
            e2 = e2in[bb] + 0.7f * gl;
        }
        out[3 * NB + bb] = e1;
        out[4 * NB + bb] = e2;
    }

    if (threadIdx.x == 0) g_ticket = 0;   // reset for next graph replay
}

extern "C" void kernel_launch(void* const* d_in, const int* in_sizes, int n_in,
                              void* d_out, int out_size) {
    const float* img  = (const float*)d_in[0];
    const float* e1in = (const float*)d_in[1];
    const float* e2in = (const float*)d_in[2];
    float* out = (float*)d_out;

    fused_kernel<<<NB * BPB, TPB>>>(img, e1in, e2in, out);
}

// round 3
// speedup vs baseline: 1.4862x; 1.1629x over previous
#include <cuda_runtime.h>

// Problem constants
#define NB    16
#define HW    (544*960)          // 522240 gray pixels per batch
#define HW4   (HW/4)             // 130560 float4 per channel per batch
#define TPB   256
#define BPB   51                 // blocks per batch
#define ITERS (HW4/(TPB*BPB))    // 10 (exact: 130560 = 256*51*10)
#define NPART (NB*BPB)           // 816

// Partial accumulators — every slot written every launch (no zeroing needed)
__device__ float g_psum[NPART];
__device__ int   g_pbright[NPART];
__device__ int   g_pdark[NPART];
__device__ int   g_ticket_b[NB];   // per-batch tickets; reset by each batch finalizer

__global__ __launch_bounds__(TPB) void fused_kernel(const float* __restrict__ img,
                                                    const float* __restrict__ e1in,
                                                    const float* __restrict__ e2in,
                                                    float* __restrict__ out) {
    const int blk   = blockIdx.x;
    const int batch = blk / BPB;
    const int bpos  = blk % BPB;

    const float4* __restrict__ c0 = (const float4*)(img + (size_t)batch * 3 * HW);
    const float4* __restrict__ c1 = c0 + HW4;
    const float4* __restrict__ c2 = c1 + HW4;

    const int base = bpos * (TPB * ITERS) + threadIdx.x;

    float sum = 0.0f;          // sum of (r+g+b); divide by 3*HW at the end
    int nb = 0, nd = 0;

    #pragma unroll
    for (int i = 0; i < ITERS; i++) {
        const int idx = base + i * TPB;
        float4 a = __ldcs(c0 + idx);
        float4 b = __ldcs(c1 + idx);
        float4 c = __ldcs(c2 + idx);

        float t0 = a.x + b.x + c.x;
        float t1 = a.y + b.y + c.y;
        float t2 = a.z + b.z + c.z;
        float t3 = a.w + b.w + c.w;

        sum += t0 + t1 + t2 + t3;
        // gray = t/3; bright: gray in [0.75, 1.0]  <=> t in [2.25, 3.0]
        nb += (t0 >= 2.25f && t0 <= 3.0f);
        nb += (t1 >= 2.25f && t1 <= 3.0f);
        nb += (t2 >= 2.25f && t2 <= 3.0f);
        nb += (t3 >= 2.25f && t3 <= 3.0f);
        // dark: gray in [0, 0.25)  <=> t in [0, 0.75)
        nd += (t0 >= 0.0f && t0 < 0.75f);
        nd += (t1 >= 0.0f && t1 < 0.75f);
        nd += (t2 >= 0.0f && t2 < 0.75f);
        nd += (t3 >= 0.0f && t3 < 0.75f);
    }

    // Warp reduce
    #pragma unroll
    for (int o = 16; o > 0; o >>= 1) {
        sum += __shfl_down_sync(0xFFFFFFFFu, sum, o);
        nb  += __shfl_down_sync(0xFFFFFFFFu, nb, o);
        nd  += __shfl_down_sync(0xFFFFFFFFu, nd, o);
    }

    // Block reduce across 8 warps
    __shared__ float ssum[TPB/32];
    __shared__ int   sbr[TPB/32], sdk[TPB/32];
    __shared__ int   s_is_last;
    __shared__ float s_bl, s_gl;
    const int wid  = threadIdx.x >> 5;
    const int lane = threadIdx.x & 31;
    if (lane == 0) { ssum[wid] = sum; sbr[wid] = nb; sdk[wid] = nd; }
    __syncthreads();
    if (wid == 0) {
        float s = (lane < TPB/32) ? ssum[lane] : 0.0f;
        int b_ = (lane < TPB/32) ? sbr[lane] : 0;
        int d_ = (lane < TPB/32) ? sdk[lane] : 0;
        #pragma unroll
        for (int o = 4; o > 0; o >>= 1) {
            s  += __shfl_down_sync(0xFFFFFFFFu, s, o);
            b_ += __shfl_down_sync(0xFFFFFFFFu, b_, o);
            d_ += __shfl_down_sync(0xFFFFFFFFu, d_, o);
        }
        if (lane == 0) {
            g_psum[blk]    = s;
            g_pbright[blk] = b_;
            g_pdark[blk]   = d_;
            __threadfence();
            int t = atomicAdd(&g_ticket_b[batch], 1);
            s_is_last = (t == BPB - 1);
        }
    }
    __syncthreads();

    if (!s_is_last) return;

    // ---- Last block of THIS batch: finalize this batch (L2-hot partials). ----
    if (wid == 0) {
        float fsum = 0.0f;
        int fb = 0, fd = 0;
        #pragma unroll
        for (int i = lane; i < BPB; i += 32) {
            fsum += g_psum[batch * BPB + i];
            fb   += g_pbright[batch * BPB + i];
            fd   += g_pdark[batch * BPB + i];
        }
        #pragma unroll
        for (int o = 16; o > 0; o >>= 1) {
            fsum += __shfl_down_sync(0xFFFFFFFFu, fsum, o);
            fb   += __shfl_down_sync(0xFFFFFFFFu, fb, o);
            fd   += __shfl_down_sync(0xFFFFFFFFu, fd, o);
        }
        if (lane == 0) {
            float dr   = (float)fb / ((float)fd + 1e-5f);
            float bavg = fsum * (1.0f / (3.0f * (float)HW));
            float g = 0.5f;
            float gap;
            if (dr > 1.0f && bavg > 0.4f && bavg < 0.6f)       gap = g * 2.0f;
            else if (bavg <= 0.3f)                             gap = g * 0.5f;
            else if (bavg >= 0.7f)                             gap = g * 0.5f;
            else if (dr <= 1.0f && bavg > 0.3f && bavg < 0.7f) gap = g * 0.75f;
            else                                               gap = 0.0f;
            out[0 * NB + batch] = dr;
            out[1 * NB + batch] = bavg;
            out[2 * NB + batch] = gap;
            s_bl = bavg;
            s_gl = gap;
            g_ticket_b[batch] = 0;   // reset for next graph replay
        }
    }
    __syncthreads();

    // Epilogue depends ONLY on the last batch's scalars — the batch-15
    // finalizer computes all of e1/e2 itself. No global serialization.
    if (batch == NB - 1 && threadIdx.x < NB) {
        const int bb = threadIdx.x;
        const float bl = s_bl;
        const float gl = s_gl;
        const float sc = 1.7f;
        float e1, e2;
        if (bl <= 0.25f) {
            e1 = e1in[bb] + 0.5f * gl * sc;
            e2 = e2in[bb] + 0.5f * gl * sc;
        } else if (bl >= 0.75f) {
            e1 = e1in[bb] - 0.5f * gl * sc;
            e2 = e2in[bb] - 0.5f * gl * sc;
        } else {
            e1 = e1in[bb] - 0.3f * gl;
            e2 = e2in[bb] + 0.7f * gl;
        }
        out[3 * NB + bb] = e1;
        out[4 * NB + bb] = e2;
    }
}

extern "C" void kernel_launch(void* const* d_in, const int* in_sizes, int n_in,
                              void* d_out, int out_size) {
    const float* img  = (const float*)d_in[0];
    const float* e1in = (const float*)d_in[1];
    const float* e2in = (const float*)d_in[2];
    float* out = (float*)d_out;

    fused_kernel<<<NB * BPB, TPB>>>(img, e1in, e2in, out);
}